// round 3
// baseline (speedup 1.0000x reference)
#include <cuda_runtime.h>
#include <math.h>

// ---------------------------------------------------------------------------
// Problem constants
// ---------------------------------------------------------------------------
#define NB      8192
#define ND      64
#define NNEG    128
#define KNBR    32

#define W1c     1e-6f
#define W3c     1e-6f
#define NEG_WEIGHTc 200.0f
#define GAMMAc  1e-4f
#define LAMBDAc 2.5f

// ---------------------------------------------------------------------------
// Scratch (device globals)
// ---------------------------------------------------------------------------
__device__ float g_M[ND * ND];     // M = W_u^T W_i
__device__ float g_cpe[ND];        // W_i^T b_u
__device__ float g_cue[ND];        // W_u^T b_i
__device__ float g_c0;             // b_u . b_i
__device__ float g_norm_partial[NB];
__device__ float g_lossL[NB];
__device__ float g_lossI[NB];
__device__ float g_mseP[NB];
__device__ unsigned g_done;

__device__ __forceinline__ float softplusf(float x) {
    return fmaxf(x, 0.0f) + __logf(1.0f + __expf(-fabsf(x)));
}

__device__ __forceinline__ float bfly(float s) {
    #pragma unroll
    for (int o = 16; o; o >>= 1) s += __shfl_xor_sync(0xFFFFFFFFu, s, o);
    return s;
}

// ---------------------------------------------------------------------------
// Kernel 1: precompute M = W_u^T W_i (+ bias terms), smem-staged.
// grid 16 x 256 : CTA k computes rows [k*4, k*4+4) of M.
// Also resets the last-block counter for this graph replay.
// ---------------------------------------------------------------------------
__global__ void __launch_bounds__(256)
precompute_kernel(const float* __restrict__ wu, const float* __restrict__ bu,
                  const float* __restrict__ wi, const float* __restrict__ bi) {
    __shared__ float swu[ND * ND];
    __shared__ float swi[ND * ND];

    const int tid = threadIdx.x;
    if (blockIdx.x == 0 && tid == 0) g_done = 0u;

    // coalesced stage: 4096 floats each = 4 float4 per thread
    {
        const float4* su = (const float4*)wu;
        const float4* si = (const float4*)wi;
        float4* du = (float4*)swu;
        float4* di = (float4*)swi;
        #pragma unroll
        for (int r = 0; r < 4; r++) {
            du[tid + r * 256] = su[tid + r * 256];
            di[tid + r * 256] = si[tid + r * 256];
        }
    }
    __syncthreads();

    const int idx = blockIdx.x * 256 + tid;
    const int a = idx >> 6;     // row of M
    const int c = idx & 63;     // col of M
    // 4-way split accumulation for ILP
    float a0 = 0.f, a1 = 0.f, a2 = 0.f, a3 = 0.f;
    #pragma unroll
    for (int d = 0; d < ND; d += 4) {
        a0 = fmaf(swu[(d + 0) * ND + a], swi[(d + 0) * ND + c], a0);
        a1 = fmaf(swu[(d + 1) * ND + a], swi[(d + 1) * ND + c], a1);
        a2 = fmaf(swu[(d + 2) * ND + a], swi[(d + 2) * ND + c], a2);
        a3 = fmaf(swu[(d + 3) * ND + a], swi[(d + 3) * ND + c], a3);
    }
    g_M[idx] = (a0 + a1) + (a2 + a3);

    if (blockIdx.x == 0 && tid < ND) {
        const int j = tid;
        float c1 = 0.0f, c2 = 0.0f;
        #pragma unroll 8
        for (int d = 0; d < ND; d++) {
            c1 = fmaf(swi[d * ND + j], bu[d], c1);
            c2 = fmaf(swu[d * ND + j], bi[d], c2);
        }
        g_cpe[j] = c1;
        g_cue[j] = c2;
        if (j == 0) {
            float s = 0.0f;
            #pragma unroll 8
            for (int d = 0; d < ND; d++) s = fmaf(bu[d], bi[d], s);
            g_c0 = s;
        }
    }
}

// ---------------------------------------------------------------------------
// Fused kernel args
// ---------------------------------------------------------------------------
struct FusedArgs {
    const int*   users;
    const int*   pos_items;
    const int*   neg_items;
    const float* rpkms;
    const float* user_emb;  long nu;
    const float* item_emb;  long ni;
    const float* beta_uD;
    const float* beta_iD;
    const int*   ii_nbr;
    const float* ii_con;
    const float* sp[8]; int sn[8];
    float* out;
};

// ---------------------------------------------------------------------------
// norm slice: grid-stride sum of squares over both big tables
// ---------------------------------------------------------------------------
__device__ __forceinline__ float norm_slice(const FusedArgs& a) {
    float acc = 0.0f;
    const size_t tg = (size_t)blockIdx.x * 256 + threadIdx.x;
    const size_t stride = (size_t)gridDim.x * 256;

    const float4* pu = (const float4*)a.user_emb;
    const size_t mu = (size_t)a.nu >> 2;
    for (size_t i = tg; i < mu; i += stride) {
        float4 v = pu[i];
        acc += v.x*v.x + v.y*v.y + v.z*v.z + v.w*v.w;
    }
    const float4* pi = (const float4*)a.item_emb;
    const size_t mi = (size_t)a.ni >> 2;
    for (size_t i = tg; i < mi; i += stride) {
        float4 v = pi[i];
        acc += v.x*v.x + v.y*v.y + v.z*v.z + v.w*v.w;
    }
    if (blockIdx.x == 0) {
        #pragma unroll
        for (int j = 0; j < 8; j++) {
            const float* q = a.sp[j];
            const int n = a.sn[j];
            for (int i = threadIdx.x; i < n; i += 256) {
                float v = q[i];
                acc += v * v;
            }
        }
    }
    return acc;
}

// ---------------------------------------------------------------------------
// per-sample work (one CTA = one sample). Assumes s_ue/s_pe preloaded + synced.
// ---------------------------------------------------------------------------
__device__ __forceinline__ void sample_work(
    const FusedArgs& a, int b, int u, int p,
    const float* s_ue, const float* s_pe, float* s_t,
    float* sN, float* sI, float* sPosLoss, float* sMse)
{
    const int tid  = threadIdx.x;
    const int lane = tid & 31;
    const int warp = tid >> 5;

    const float  bu  = __ldg(a.beta_uD + u);
    const float2 uev = make_float2(s_ue[2 * lane], s_ue[2 * lane + 1]);

    // ---- negatives: warp handles 16, unroll 4 (MLP=4, ILP'd shuffles) ----
    float accN = 0.0f;
    const int* negb = a.neg_items + (size_t)b * NNEG + warp * 16;
    #pragma unroll
    for (int n = 0; n < 16; n += 4) {
        const int i0 = negb[n + 0];
        const int i1 = negb[n + 1];
        const int i2 = negb[n + 2];
        const int i3 = negb[n + 3];
        const float2 v0 = __ldg((const float2*)(a.item_emb + (size_t)i0 * ND) + lane);
        const float2 v1 = __ldg((const float2*)(a.item_emb + (size_t)i1 * ND) + lane);
        const float2 v2 = __ldg((const float2*)(a.item_emb + (size_t)i2 * ND) + lane);
        const float2 v3 = __ldg((const float2*)(a.item_emb + (size_t)i3 * ND) + lane);
        const float bi0 = __ldg(a.beta_iD + i0);
        const float bi1 = __ldg(a.beta_iD + i1);
        const float bi2 = __ldg(a.beta_iD + i2);
        const float bi3 = __ldg(a.beta_iD + i3);
        float s0 = fmaf(v0.x, uev.x, v0.y * uev.y);
        float s1 = fmaf(v1.x, uev.x, v1.y * uev.y);
        float s2 = fmaf(v2.x, uev.x, v2.y * uev.y);
        float s3 = fmaf(v3.x, uev.x, v3.y * uev.y);
        #pragma unroll
        for (int o = 16; o; o >>= 1) {
            s0 += __shfl_xor_sync(0xFFFFFFFFu, s0, o);
            s1 += __shfl_xor_sync(0xFFFFFFFFu, s1, o);
            s2 += __shfl_xor_sync(0xFFFFFFFFu, s2, o);
            s3 += __shfl_xor_sync(0xFFFFFFFFu, s3, o);
        }
        accN += fmaf(bu, bi0, W3c) * softplusf(s0)
              + fmaf(bu, bi1, W3c) * softplusf(s1)
              + fmaf(bu, bi2, W3c) * softplusf(s2)
              + fmaf(bu, bi3, W3c) * softplusf(s3);
    }

    // ---- neighbors: warp handles 4, fully unrolled ----
    float accI = 0.0f;
    {
        const int*   nbrp = a.ii_nbr + (size_t)p * KNBR + warp * 4;
        const float* simp = a.ii_con + (size_t)p * KNBR + warp * 4;
        const int j0 = nbrp[0];
        const int j1 = nbrp[1];
        const int j2 = nbrp[2];
        const int j3 = nbrp[3];
        const float2 v0 = __ldg((const float2*)(a.item_emb + (size_t)j0 * ND) + lane);
        const float2 v1 = __ldg((const float2*)(a.item_emb + (size_t)j1 * ND) + lane);
        const float2 v2 = __ldg((const float2*)(a.item_emb + (size_t)j2 * ND) + lane);
        const float2 v3 = __ldg((const float2*)(a.item_emb + (size_t)j3 * ND) + lane);
        float s0 = fmaf(v0.x, uev.x, v0.y * uev.y);
        float s1 = fmaf(v1.x, uev.x, v1.y * uev.y);
        float s2 = fmaf(v2.x, uev.x, v2.y * uev.y);
        float s3 = fmaf(v3.x, uev.x, v3.y * uev.y);
        #pragma unroll
        for (int o = 16; o; o >>= 1) {
            s0 += __shfl_xor_sync(0xFFFFFFFFu, s0, o);
            s1 += __shfl_xor_sync(0xFFFFFFFFu, s1, o);
            s2 += __shfl_xor_sync(0xFFFFFFFFu, s2, o);
            s3 += __shfl_xor_sync(0xFFFFFFFFu, s3, o);
        }
        accI += simp[0] * softplusf(-s0) + simp[1] * softplusf(-s1)
              + simp[2] * softplusf(-s2) + simp[3] * softplusf(-s3);
    }

    if (lane == 0) { sN[warp] = accN; sI[warp] = accI; }

    // ---- matvec t = M^T ue (+cpe) : coalesced over 64 threads ----
    if (tid < ND) {
        float acc = g_cpe[tid];
        #pragma unroll 16
        for (int d = 0; d < ND; d++)
            acc = fmaf(s_ue[d], g_M[d * ND + tid], acc);
        s_t[tid] = acc;
    }

    // ---- positive score (warp 2, concurrent with matvec) ----
    if (warp == 2) {
        const float2 pv = make_float2(s_pe[2 * lane], s_pe[2 * lane + 1]);
        float s = fmaf(pv.x, uev.x, pv.y * uev.y);
        s = bfly(s);
        if (lane == 0) {
            const float bip = __ldg(a.beta_iD + p);
            *sPosLoss = fmaf(bu, bip, W1c) * softplusf(-s);
        }
    }
    __syncthreads();

    // ---- mse (warp 0) ----
    if (warp == 0) {
        float v = s_t[2*lane] * s_pe[2*lane] + s_t[2*lane+1] * s_pe[2*lane+1]
                + g_cue[2*lane] * s_ue[2*lane] + g_cue[2*lane+1] * s_ue[2*lane+1];
        v = bfly(v);
        if (lane == 0) {
            const float pred = v + g_c0;
            const float dlt = pred - __ldg(a.rpkms + b);
            *sMse = dlt * dlt;
        }
    }
    __syncthreads();

    if (tid == 0) {
        float sn = 0.0f, si = 0.0f;
        #pragma unroll
        for (int w = 0; w < 8; w++) { sn += sN[w]; si += sI[w]; }
        g_lossL[b] = *sPosLoss + NEG_WEIGHTc * (sn * (1.0f / NNEG));
        g_lossI[b] = si;
        g_mseP[b]  = *sMse;
    }
}

// ---------------------------------------------------------------------------
// Fused kernel: one CTA per sample + grid-stride norm slice.
// Last CTA to finish performs the deterministic final reduction.
// ---------------------------------------------------------------------------
__global__ void __launch_bounds__(256)
fused_kernel(FusedArgs a) {
    const int b = blockIdx.x;
    const int tid = threadIdx.x;

    __shared__ float s_ue[ND];
    __shared__ float s_pe[ND];
    __shared__ float s_t[ND];
    __shared__ float sN[8], sI[8];
    __shared__ float sPosLoss, sMse;
    __shared__ float sNorm[8];
    __shared__ bool  sLast;

    const int u = __ldg(a.users + b);
    const int p = __ldg(a.pos_items + b);
    if (tid < ND)          s_ue[tid]      = __ldg(a.user_emb + (size_t)u * ND + tid);
    else if (tid < 2 * ND) s_pe[tid - ND] = __ldg(a.item_emb + (size_t)p * ND + (tid - ND));
    __syncthreads();

    float nacc;
    if (b & 1) {
        nacc = norm_slice(a);
        sample_work(a, b, u, p, s_ue, s_pe, s_t, sN, sI, &sPosLoss, &sMse);
    } else {
        sample_work(a, b, u, p, s_ue, s_pe, s_t, sN, sI, &sPosLoss, &sMse);
        nacc = norm_slice(a);
    }

    // CTA-reduce the norm partial
    nacc = bfly(nacc);
    if ((tid & 31) == 0) sNorm[tid >> 5] = nacc;
    __syncthreads();
    if (tid == 0) {
        float v = 0.0f;
        #pragma unroll
        for (int w = 0; w < 8; w++) v += sNorm[w];
        g_norm_partial[b] = v;
    }

    // ---- last-block finalize ----
    __threadfence();
    if (tid == 0) sLast = (atomicAdd(&g_done, 1u) == (unsigned)(NB - 1));
    __syncthreads();
    if (!sLast) return;
    __threadfence();

    double aL = 0.0, aI = 0.0, aM = 0.0, aN = 0.0;
    for (int i = tid; i < NB; i += 256) {
        aL += (double)g_lossL[i];
        aI += (double)g_lossI[i];
        aM += (double)g_mseP[i];
        aN += (double)g_norm_partial[i];
    }
    __shared__ double rL[256], rI[256], rM[256], rN[256];
    rL[tid] = aL; rI[tid] = aI; rM[tid] = aM; rN[tid] = aN;
    __syncthreads();
    for (int o = 128; o; o >>= 1) {
        if (tid < o) {
            rL[tid] += rL[tid + o];
            rI[tid] += rI[tid + o];
            rM[tid] += rM[tid + o];
            rN[tid] += rN[tid + o];
        }
        __syncthreads();
    }
    if (tid == 0) {
        const double lossL = rL[0] / (double)NB;
        const double lossI = rI[0] * ((double)LAMBDAc / ((double)NB * (double)KNBR));
        const double mse   = rM[0] / (double)NB;
        const double norm  = rN[0] * 0.5 * (double)GAMMAc;
        float* out = a.out;
        out[0] = (float)(lossL + lossI + mse + norm);
        out[1] = (float)lossL;
        out[2] = (float)lossI;
        out[3] = 0.0f;
        out[4] = (float)mse;
        out[5] = (float)norm;
    }
}

// ---------------------------------------------------------------------------
// Launch
// ---------------------------------------------------------------------------
extern "C" void kernel_launch(void* const* d_in, const int* in_sizes, int n_in,
                              void* d_out, int out_size) {
    FusedArgs a;
    a.users     = (const int*)d_in[0];
    a.pos_items = (const int*)d_in[1];
    a.neg_items = (const int*)d_in[2];
    a.rpkms     = (const float*)d_in[3];
    a.user_emb  = (const float*)d_in[4];  a.nu = in_sizes[4];
    a.item_emb  = (const float*)d_in[5];  a.ni = in_sizes[5];
    a.beta_uD   = (const float*)d_in[6];
    a.beta_iD   = (const float*)d_in[7];
    a.ii_nbr    = (const int*)d_in[8];
    a.ii_con    = (const float*)d_in[9];
    const float* mse_u_w = (const float*)d_in[10];
    const float* mse_u_b = (const float*)d_in[11];
    const float* mse_i_w = (const float*)d_in[12];
    const float* mse_i_b = (const float*)d_in[13];
    a.sp[0] = mse_u_w;               a.sn[0] = in_sizes[10];
    a.sp[1] = mse_u_b;               a.sn[1] = in_sizes[11];
    a.sp[2] = mse_i_w;               a.sn[2] = in_sizes[12];
    a.sp[3] = mse_i_b;               a.sn[3] = in_sizes[13];
    a.sp[4] = (const float*)d_in[14]; a.sn[4] = in_sizes[14];
    a.sp[5] = (const float*)d_in[15]; a.sn[5] = in_sizes[15];
    a.sp[6] = (const float*)d_in[16]; a.sn[6] = in_sizes[16];
    a.sp[7] = (const float*)d_in[17]; a.sn[7] = in_sizes[17];
    a.out   = (float*)d_out;

    precompute_kernel<<<16, 256>>>(mse_u_w, mse_u_b, mse_i_w, mse_i_b);
    fused_kernel<<<NB, 256>>>(a);
}